// round 14
// baseline (speedup 1.0000x reference)
#include <cuda_runtime.h>
#include <math.h>

static constexpr int BATCH   = 8192;
static constexpr int NPTS    = 2048;
static constexpr int THREADS = 256;               // 8 warps/CTA
static constexpr int WARPS_PER_CTA = THREADS / 32;
static constexpr int ITERS = NPTS / (32 * 4);     // 16 float4 iterations per lane
static constexpr int BPW   = 4;                   // batches per warp (pipelined)
static constexpr int NWARPS_TOTAL = BATCH / BPW;  // 2048
static constexpr int GRID  = NWARPS_TOTAL / WARPS_PER_CTA;   // 256 CTAs -> 1 wave

// evict-first streaming load (read-once data)
__device__ __forceinline__ float4 ldcs4(const float4* p) { return __ldcs(p); }

// ---------------------------------------------------------------------------
// Signed cofactor of 4x4 matrix M with row r, col c removed (constant indices
// -> fully folded at compile time under unrolling).
// ---------------------------------------------------------------------------
__device__ __forceinline__ float cof4(const float M[4][4], int r, int c)
{
    int ri[3], ci[3];
    int k = 0;
#pragma unroll
    for (int i = 0; i < 4; i++) if (i != r) ri[k++] = i;
    k = 0;
#pragma unroll
    for (int j = 0; j < 4; j++) if (j != c) ci[k++] = j;
    const float a = M[ri[0]][ci[0]], b = M[ri[0]][ci[1]], cc = M[ri[0]][ci[2]];
    const float d = M[ri[1]][ci[0]], e = M[ri[1]][ci[1]], f  = M[ri[1]][ci[2]];
    const float g = M[ri[2]][ci[0]], h = M[ri[2]][ci[1]], ii = M[ri[2]][ci[2]];
    const float det = a * (e * ii - f * h) - b * (d * ii - f * g) + cc * (d * h - e * g);
    return ((r + c) & 1) ? -det : det;
}

// accumulate one float4 group of the 16 moments
__device__ __forceinline__ void accum16(float acc[16],
                                        const float4& vw,
                                        const float4& vax, const float4& vay, const float4& vaz,
                                        const float4& vbx, const float4& vby, const float4& vbz)
{
    const float wv[4]  = {vw.x,  vw.y,  vw.z,  vw.w};
    const float axv[4] = {vax.x, vax.y, vax.z, vax.w};
    const float ayv[4] = {vay.x, vay.y, vay.z, vay.w};
    const float azv[4] = {vaz.x, vaz.y, vaz.z, vaz.w};
    const float bxv[4] = {vbx.x, vbx.y, vbx.z, vbx.w};
    const float byv[4] = {vby.x, vby.y, vby.z, vby.w};
    const float bzv[4] = {vbz.x, vbz.y, vbz.z, vbz.w};
#pragma unroll
    for (int j = 0; j < 4; j++) {
        const float wi  = wv[j];
        const float wax = wi * axv[j];
        const float way = wi * ayv[j];
        const float waz = wi * azv[j];
        acc[0] += wi;
        acc[1] += wax;
        acc[2] += way;
        acc[3] += waz;
        acc[4]  = fmaf(wi,  bxv[j], acc[4]);
        acc[5]  = fmaf(wi,  byv[j], acc[5]);
        acc[6]  = fmaf(wi,  bzv[j], acc[6]);
        acc[7]  = fmaf(wax, bxv[j], acc[7]);
        acc[8]  = fmaf(wax, byv[j], acc[8]);
        acc[9]  = fmaf(wax, bzv[j], acc[9]);
        acc[10] = fmaf(way, bxv[j], acc[10]);
        acc[11] = fmaf(way, byv[j], acc[11]);
        acc[12] = fmaf(way, bzv[j], acc[12]);
        acc[13] = fmaf(waz, bxv[j], acc[13]);
        acc[14] = fmaf(waz, byv[j], acc[14]);
        acc[15] = fmaf(waz, bzv[j], acc[15]);
    }
}

// QCP epilogue: moments -> R (9) and t (3), scattered by lanes 0-11.
__device__ __forceinline__ void qcp_write(const float acc[16], int b, int lane,
                                          float* __restrict__ out)
{
    const float Ssum = acc[0] + 1e-5f;
    const float inv  = __fdividef(1.f, Ssum);
    const float Wn   = acc[0] * inv;
    const float ca[3] = {acc[1] * inv, acc[2] * inv, acc[3] * inv};
    const float cb[3] = {acc[4] * inv, acc[5] * inv, acc[6] * inv};

    // cov[d][e] = Sab[d][e]/S - ca_d*cb_e*(2 - Wn)
    float cov[3][3];
    const float fac = 2.f - Wn;
#pragma unroll
    for (int d = 0; d < 3; d++)
#pragma unroll
        for (int e = 0; e < 3; e++)
            cov[d][e] = acc[7 + 3 * d + e] * inv - ca[d] * cb[e] * fac;

    const float Sxx = cov[0][0], Sxy = cov[0][1], Sxz = cov[0][2];
    const float Syx = cov[1][0], Syy = cov[1][1], Syz = cov[1][2];
    const float Szx = cov[2][0], Szy = cov[2][1], Szz = cov[2][2];

    // Horn's 4x4 symmetric traceless matrix N (quaternion order w,x,y,z)
    float N[4][4];
    N[0][0] =  Sxx + Syy + Szz;
    N[0][1] =  Syz - Szy;
    N[0][2] =  Szx - Sxz;
    N[0][3] =  Sxy - Syx;
    N[1][1] =  Sxx - Syy - Szz;
    N[1][2] =  Sxy + Syx;
    N[1][3] =  Szx + Sxz;
    N[2][2] = -Sxx + Syy - Szz;
    N[2][3] =  Syz + Szy;
    N[3][3] = -Sxx - Syy + Szz;
    N[1][0] = N[0][1]; N[2][0] = N[0][2]; N[3][0] = N[0][3];
    N[2][1] = N[1][2]; N[3][1] = N[1][3]; N[3][2] = N[2][3];

    // characteristic polynomial of N (traceless): P(l) = l^4 + e2 l^2 - e3 l + e4
    float e2 = 0.f;
#pragma unroll
    for (int i = 0; i < 4; i++)
#pragma unroll
        for (int j = i + 1; j < 4; j++)
            e2 += N[i][i] * N[j][j] - N[i][j] * N[i][j];

    float e3 = cof4(N, 0, 0) + cof4(N, 1, 1) + cof4(N, 2, 2) + cof4(N, 3, 3);

    float e4 = N[0][0] * cof4(N, 0, 0) + N[0][1] * cof4(N, 0, 1)
             + N[0][2] * cof4(N, 0, 2) + N[0][3] * cof4(N, 0, 3);

    // Newton for the largest root, starting from ||N||_F >= lambda_max
    float fro2 = 0.f;
#pragma unroll
    for (int i = 0; i < 4; i++)
#pragma unroll
        for (int j = 0; j < 4; j++) fro2 += N[i][j] * N[i][j];
    float lam = fro2 * rsqrtf(fro2 + 1e-38f);     // ~ ||N||_F  (MUFU)

#pragma unroll
    for (int it = 0; it < 12; it++) {
        const float l2 = lam * lam;
        const float P  = fmaf(fmaf(l2, 1.f, e2), l2, fmaf(-e3, lam, e4));
        const float Pp = fmaf(fmaf(4.f, l2, 2.f * e2), lam, -e3);
        lam -= __fdividef(P, Pp + copysignf(1e-30f, Pp));
    }

    // B = N - lam*I; adj(B) ~ v v^T (rank-3). Take max-norm column as quaternion.
    float B[4][4];
#pragma unroll
    for (int i = 0; i < 4; i++)
#pragma unroll
        for (int j = 0; j < 4; j++)
            B[i][j] = N[i][j] - (i == j ? lam : 0.f);

    float adj[4][4];
#pragma unroll
    for (int i = 0; i < 4; i++)
#pragma unroll
        for (int j = i; j < 4; j++) {
            const float c = cof4(B, j, i);      // adj[i][j] = C[j][i]
            adj[i][j] = c;
            adj[j][i] = c;                       // adj of symmetric is symmetric
        }

    float bestn = -1.f;
    float q0 = 1.f, qx = 0.f, qy = 0.f, qz = 0.f;
#pragma unroll
    for (int j = 0; j < 4; j++) {
        const float n2 = adj[0][j] * adj[0][j] + adj[1][j] * adj[1][j]
                       + adj[2][j] * adj[2][j] + adj[3][j] * adj[3][j];
        const bool gt = n2 > bestn;
        bestn = gt ? n2 : bestn;
        q0 = gt ? adj[0][j] : q0;
        qx = gt ? adj[1][j] : qx;
        qy = gt ? adj[2][j] : qy;
        qz = gt ? adj[3][j] : qz;
    }

    // rotation from UNNORMALIZED quaternion: s = 2 / (q.q)
    const float s2 = __fdividef(2.f, q0 * q0 + qx * qx + qy * qy + qz * qz + 1e-38f);

    float Rf[9];
    Rf[0] = 1.f - s2 * (qy * qy + qz * qz);
    Rf[1] = s2 * (qx * qy - q0 * qz);
    Rf[2] = s2 * (qx * qz + q0 * qy);
    Rf[3] = s2 * (qx * qy + q0 * qz);
    Rf[4] = 1.f - s2 * (qx * qx + qz * qz);
    Rf[5] = s2 * (qy * qz - q0 * qx);
    Rf[6] = s2 * (qx * qz - q0 * qy);
    Rf[7] = s2 * (qy * qz + q0 * qx);
    Rf[8] = 1.f - s2 * (qx * qx + qy * qy);

    float tr[3];
#pragma unroll
    for (int i = 0; i < 3; i++)
        tr[i] = cb[i] - (Rf[3 * i + 0] * ca[0] + Rf[3 * i + 1] * ca[1]
                       + Rf[3 * i + 2] * ca[2]);

    // parallel scatter: lanes 0-8 write R, lanes 9-11 write t
    if (lane < 9) {
        out[(size_t)b * 9 + lane] = Rf[lane];
    } else if (lane < 12) {
        out[(size_t)BATCH * 9 + (size_t)b * 3 + (lane - 9)] = tr[lane - 9];
    }
}

// ---------------------------------------------------------------------------
// Fused kernel, 4 batches per warp, cross-batch pipelined, single wave.
// Next-batch prime loads issue BEFORE the butterfly reduce so they have the
// reduce window (~500 cyc of SHFL latency) + the QCP window to land.
// ---------------------------------------------------------------------------
__global__ void __launch_bounds__(THREADS, 2)
kabsch_fused_kernel(const float* __restrict__ src,
                    const float* __restrict__ corr,
                    const float* __restrict__ wts,
                    float* __restrict__ out)
{
    const int lane  = threadIdx.x & 31;
    const int wslot = blockIdx.x * WARPS_PER_CTA + (threadIdx.x >> 5);  // 0..2047

    // prime batch 0 of this warp
    int b = wslot;
    size_t base3 = (size_t)b * 3 * NPTS;
    const float4* ax = (const float4*)(src  + base3);
    const float4* ay = (const float4*)(src  + base3 + NPTS);
    const float4* az = (const float4*)(src  + base3 + 2 * NPTS);
    const float4* bx = (const float4*)(corr + base3);
    const float4* by = (const float4*)(corr + base3 + NPTS);
    const float4* bz = (const float4*)(corr + base3 + 2 * NPTS);
    const float4* wp = (const float4*)(wts  + (size_t)b * NPTS);

    float4 cw  = ldcs4(wp + lane);
    float4 cax = ldcs4(ax + lane), cay = ldcs4(ay + lane), caz = ldcs4(az + lane);
    float4 cbx = ldcs4(bx + lane), cby = ldcs4(by + lane), cbz = ldcs4(bz + lane);

#pragma unroll
    for (int bpi = 0; bpi < BPW; bpi++) {
        float acc[16];
#pragma unroll
        for (int i = 0; i < 16; i++) acc[i] = 0.f;

        // streaming loop for the current batch (primed regs hold iter 0)
#pragma unroll 2
        for (int it = 0; it < ITERS - 1; it++) {
            const int idx = lane + 32 * (it + 1);
            const float4 nw  = ldcs4(wp + idx);
            const float4 nax = ldcs4(ax + idx);
            const float4 nay = ldcs4(ay + idx);
            const float4 naz = ldcs4(az + idx);
            const float4 nbx = ldcs4(bx + idx);
            const float4 nby = ldcs4(by + idx);
            const float4 nbz = ldcs4(bz + idx);

            accum16(acc, cw, cax, cay, caz, cbx, cby, cbz);

            cw = nw; cax = nax; cay = nay; caz = naz;
            cbx = nbx; cby = nby; cbz = nbz;
        }
        // peeled final iteration — after this, acc is final and cw..cbz are dead
        accum16(acc, cw, cax, cay, caz, cbx, cby, cbz);

        const int b_cur = b;

        // prime the NEXT batch FIRST: its DRAM latency overlaps both the
        // butterfly reduce below and the QCP epilogue
        if (bpi + 1 < BPW) {
            b = wslot + (bpi + 1) * NWARPS_TOTAL;
            base3 = (size_t)b * 3 * NPTS;
            ax = (const float4*)(src  + base3);
            ay = (const float4*)(src  + base3 + NPTS);
            az = (const float4*)(src  + base3 + 2 * NPTS);
            bx = (const float4*)(corr + base3);
            by = (const float4*)(corr + base3 + NPTS);
            bz = (const float4*)(corr + base3 + 2 * NPTS);
            wp = (const float4*)(wts  + (size_t)b * NPTS);

            cw  = ldcs4(wp + lane);
            cax = ldcs4(ax + lane); cay = ldcs4(ay + lane); caz = ldcs4(az + lane);
            cbx = ldcs4(bx + lane); cby = ldcs4(by + lane); cbz = ldcs4(bz + lane);
        }

        // butterfly reduce: ALL lanes end with the complete 16 moments
#pragma unroll
        for (int i = 0; i < 16; i++) {
#pragma unroll
            for (int off = 16; off; off >>= 1)
                acc[i] += __shfl_xor_sync(0xffffffffu, acc[i], off);
        }

        // epilogue for the current batch (overlaps the primed loads above)
        qcp_write(acc, b_cur, lane, out);
    }
}

extern "C" void kernel_launch(void* const* d_in, const int* in_sizes, int n_in,
                              void* d_out, int out_size)
{
    const float* src  = (const float*)d_in[0];
    const float* corr = (const float*)d_in[1];
    const float* wts  = (const float*)d_in[2];
    float* out = (float*)d_out;

    kabsch_fused_kernel<<<GRID, THREADS>>>(src, corr, wts, out);
}

// round 15
// speedup vs baseline: 1.0237x; 1.0237x over previous
#include <cuda_runtime.h>
#include <math.h>

static constexpr int BATCH   = 8192;
static constexpr int NPTS    = 2048;
static constexpr int THREADS = 128;               // 4 warps/CTA: finer placement grain
static constexpr int WARPS_PER_CTA = THREADS / 32;
static constexpr int ITERS = NPTS / (32 * 4);     // 16 float4 iterations per lane
static constexpr int BPW   = 4;                   // batches per warp (pipelined)
static constexpr int NWARPS_TOTAL = BATCH / BPW;  // 2048
static constexpr int GRID  = NWARPS_TOTAL / WARPS_PER_CTA;   // 512 CTAs

// evict-first streaming load (read-once data)
__device__ __forceinline__ float4 ldcs4(const float4* p) { return __ldcs(p); }

// ---------------------------------------------------------------------------
// Signed cofactor of 4x4 matrix M with row r, col c removed (constant indices
// -> fully folded at compile time under unrolling).
// ---------------------------------------------------------------------------
__device__ __forceinline__ float cof4(const float M[4][4], int r, int c)
{
    int ri[3], ci[3];
    int k = 0;
#pragma unroll
    for (int i = 0; i < 4; i++) if (i != r) ri[k++] = i;
    k = 0;
#pragma unroll
    for (int j = 0; j < 4; j++) if (j != c) ci[k++] = j;
    const float a = M[ri[0]][ci[0]], b = M[ri[0]][ci[1]], cc = M[ri[0]][ci[2]];
    const float d = M[ri[1]][ci[0]], e = M[ri[1]][ci[1]], f  = M[ri[1]][ci[2]];
    const float g = M[ri[2]][ci[0]], h = M[ri[2]][ci[1]], ii = M[ri[2]][ci[2]];
    const float det = a * (e * ii - f * h) - b * (d * ii - f * g) + cc * (d * h - e * g);
    return ((r + c) & 1) ? -det : det;
}

// accumulate one float4 group of the 16 moments
__device__ __forceinline__ void accum16(float acc[16],
                                        const float4& vw,
                                        const float4& vax, const float4& vay, const float4& vaz,
                                        const float4& vbx, const float4& vby, const float4& vbz)
{
    const float wv[4]  = {vw.x,  vw.y,  vw.z,  vw.w};
    const float axv[4] = {vax.x, vax.y, vax.z, vax.w};
    const float ayv[4] = {vay.x, vay.y, vay.z, vay.w};
    const float azv[4] = {vaz.x, vaz.y, vaz.z, vaz.w};
    const float bxv[4] = {vbx.x, vbx.y, vbx.z, vbx.w};
    const float byv[4] = {vby.x, vby.y, vby.z, vby.w};
    const float bzv[4] = {vbz.x, vbz.y, vbz.z, vbz.w};
#pragma unroll
    for (int j = 0; j < 4; j++) {
        const float wi  = wv[j];
        const float wax = wi * axv[j];
        const float way = wi * ayv[j];
        const float waz = wi * azv[j];
        acc[0] += wi;
        acc[1] += wax;
        acc[2] += way;
        acc[3] += waz;
        acc[4]  = fmaf(wi,  bxv[j], acc[4]);
        acc[5]  = fmaf(wi,  byv[j], acc[5]);
        acc[6]  = fmaf(wi,  bzv[j], acc[6]);
        acc[7]  = fmaf(wax, bxv[j], acc[7]);
        acc[8]  = fmaf(wax, byv[j], acc[8]);
        acc[9]  = fmaf(wax, bzv[j], acc[9]);
        acc[10] = fmaf(way, bxv[j], acc[10]);
        acc[11] = fmaf(way, byv[j], acc[11]);
        acc[12] = fmaf(way, bzv[j], acc[12]);
        acc[13] = fmaf(waz, bxv[j], acc[13]);
        acc[14] = fmaf(waz, byv[j], acc[14]);
        acc[15] = fmaf(waz, bzv[j], acc[15]);
    }
}

// QCP epilogue: moments -> R (9) and t (3), scattered by lanes 0-11.
__device__ __forceinline__ void qcp_write(const float acc[16], int b, int lane,
                                          float* __restrict__ out)
{
    const float Ssum = acc[0] + 1e-5f;
    const float inv  = __fdividef(1.f, Ssum);
    const float Wn   = acc[0] * inv;
    const float ca[3] = {acc[1] * inv, acc[2] * inv, acc[3] * inv};
    const float cb[3] = {acc[4] * inv, acc[5] * inv, acc[6] * inv};

    // cov[d][e] = Sab[d][e]/S - ca_d*cb_e*(2 - Wn)
    float cov[3][3];
    const float fac = 2.f - Wn;
#pragma unroll
    for (int d = 0; d < 3; d++)
#pragma unroll
        for (int e = 0; e < 3; e++)
            cov[d][e] = acc[7 + 3 * d + e] * inv - ca[d] * cb[e] * fac;

    const float Sxx = cov[0][0], Sxy = cov[0][1], Sxz = cov[0][2];
    const float Syx = cov[1][0], Syy = cov[1][1], Syz = cov[1][2];
    const float Szx = cov[2][0], Szy = cov[2][1], Szz = cov[2][2];

    // Horn's 4x4 symmetric traceless matrix N (quaternion order w,x,y,z)
    float N[4][4];
    N[0][0] =  Sxx + Syy + Szz;
    N[0][1] =  Syz - Szy;
    N[0][2] =  Szx - Sxz;
    N[0][3] =  Sxy - Syx;
    N[1][1] =  Sxx - Syy - Szz;
    N[1][2] =  Sxy + Syx;
    N[1][3] =  Szx + Sxz;
    N[2][2] = -Sxx + Syy - Szz;
    N[2][3] =  Syz + Szy;
    N[3][3] = -Sxx - Syy + Szz;
    N[1][0] = N[0][1]; N[2][0] = N[0][2]; N[3][0] = N[0][3];
    N[2][1] = N[1][2]; N[3][1] = N[1][3]; N[3][2] = N[2][3];

    // characteristic polynomial of N (traceless): P(l) = l^4 + e2 l^2 - e3 l + e4
    float e2 = 0.f;
#pragma unroll
    for (int i = 0; i < 4; i++)
#pragma unroll
        for (int j = i + 1; j < 4; j++)
            e2 += N[i][i] * N[j][j] - N[i][j] * N[i][j];

    float e3 = cof4(N, 0, 0) + cof4(N, 1, 1) + cof4(N, 2, 2) + cof4(N, 3, 3);

    float e4 = N[0][0] * cof4(N, 0, 0) + N[0][1] * cof4(N, 0, 1)
             + N[0][2] * cof4(N, 0, 2) + N[0][3] * cof4(N, 0, 3);

    // Newton for the largest root, starting from ||N||_F >= lambda_max
    float fro2 = 0.f;
#pragma unroll
    for (int i = 0; i < 4; i++)
#pragma unroll
        for (int j = 0; j < 4; j++) fro2 += N[i][j] * N[i][j];
    float lam = fro2 * rsqrtf(fro2 + 1e-38f);     // ~ ||N||_F  (MUFU)

#pragma unroll
    for (int it = 0; it < 12; it++) {
        const float l2 = lam * lam;
        const float P  = fmaf(fmaf(l2, 1.f, e2), l2, fmaf(-e3, lam, e4));
        const float Pp = fmaf(fmaf(4.f, l2, 2.f * e2), lam, -e3);
        lam -= __fdividef(P, Pp + copysignf(1e-30f, Pp));
    }

    // B = N - lam*I; adj(B) ~ v v^T (rank-3). Take max-norm column as quaternion.
    float B[4][4];
#pragma unroll
    for (int i = 0; i < 4; i++)
#pragma unroll
        for (int j = 0; j < 4; j++)
            B[i][j] = N[i][j] - (i == j ? lam : 0.f);

    float adj[4][4];
#pragma unroll
    for (int i = 0; i < 4; i++)
#pragma unroll
        for (int j = i; j < 4; j++) {
            const float c = cof4(B, j, i);      // adj[i][j] = C[j][i]
            adj[i][j] = c;
            adj[j][i] = c;                       // adj of symmetric is symmetric
        }

    float bestn = -1.f;
    float q0 = 1.f, qx = 0.f, qy = 0.f, qz = 0.f;
#pragma unroll
    for (int j = 0; j < 4; j++) {
        const float n2 = adj[0][j] * adj[0][j] + adj[1][j] * adj[1][j]
                       + adj[2][j] * adj[2][j] + adj[3][j] * adj[3][j];
        const bool gt = n2 > bestn;
        bestn = gt ? n2 : bestn;
        q0 = gt ? adj[0][j] : q0;
        qx = gt ? adj[1][j] : qx;
        qy = gt ? adj[2][j] : qy;
        qz = gt ? adj[3][j] : qz;
    }

    // rotation from UNNORMALIZED quaternion: s = 2 / (q.q)
    const float s2 = __fdividef(2.f, q0 * q0 + qx * qx + qy * qy + qz * qz + 1e-38f);

    float Rf[9];
    Rf[0] = 1.f - s2 * (qy * qy + qz * qz);
    Rf[1] = s2 * (qx * qy - q0 * qz);
    Rf[2] = s2 * (qx * qz + q0 * qy);
    Rf[3] = s2 * (qx * qy + q0 * qz);
    Rf[4] = 1.f - s2 * (qx * qx + qz * qz);
    Rf[5] = s2 * (qy * qz - q0 * qx);
    Rf[6] = s2 * (qx * qz - q0 * qy);
    Rf[7] = s2 * (qy * qz + q0 * qx);
    Rf[8] = 1.f - s2 * (qx * qx + qy * qy);

    float tr[3];
#pragma unroll
    for (int i = 0; i < 3; i++)
        tr[i] = cb[i] - (Rf[3 * i + 0] * ca[0] + Rf[3 * i + 1] * ca[1]
                       + Rf[3 * i + 2] * ca[2]);

    // parallel scatter: lanes 0-8 write R, lanes 9-11 write t
    if (lane < 9) {
        out[(size_t)b * 9 + lane] = Rf[lane];
    } else if (lane < 12) {
        out[(size_t)BATCH * 9 + (size_t)b * 3 + (lane - 9)] = tr[lane - 9];
    }
}

// ---------------------------------------------------------------------------
// Fused kernel, 4 batches per warp, cross-batch pipelined, 128-thread CTAs
// for finer per-SM placement granularity (4 CTAs/SM, imbalance 1.33x vs 2x).
// ---------------------------------------------------------------------------
__global__ void __launch_bounds__(THREADS, 2)
kabsch_fused_kernel(const float* __restrict__ src,
                    const float* __restrict__ corr,
                    const float* __restrict__ wts,
                    float* __restrict__ out)
{
    const int lane  = threadIdx.x & 31;
    const int wslot = blockIdx.x * WARPS_PER_CTA + (threadIdx.x >> 5);  // 0..2047

    // prime batch 0 of this warp
    int b = wslot;
    size_t base3 = (size_t)b * 3 * NPTS;
    const float4* ax = (const float4*)(src  + base3);
    const float4* ay = (const float4*)(src  + base3 + NPTS);
    const float4* az = (const float4*)(src  + base3 + 2 * NPTS);
    const float4* bx = (const float4*)(corr + base3);
    const float4* by = (const float4*)(corr + base3 + NPTS);
    const float4* bz = (const float4*)(corr + base3 + 2 * NPTS);
    const float4* wp = (const float4*)(wts  + (size_t)b * NPTS);

    float4 cw  = ldcs4(wp + lane);
    float4 cax = ldcs4(ax + lane), cay = ldcs4(ay + lane), caz = ldcs4(az + lane);
    float4 cbx = ldcs4(bx + lane), cby = ldcs4(by + lane), cbz = ldcs4(bz + lane);

#pragma unroll
    for (int bpi = 0; bpi < BPW; bpi++) {
        float acc[16];
#pragma unroll
        for (int i = 0; i < 16; i++) acc[i] = 0.f;

        // streaming loop for the current batch (primed regs hold iter 0)
#pragma unroll 2
        for (int it = 0; it < ITERS - 1; it++) {
            const int idx = lane + 32 * (it + 1);
            const float4 nw  = ldcs4(wp + idx);
            const float4 nax = ldcs4(ax + idx);
            const float4 nay = ldcs4(ay + idx);
            const float4 naz = ldcs4(az + idx);
            const float4 nbx = ldcs4(bx + idx);
            const float4 nby = ldcs4(by + idx);
            const float4 nbz = ldcs4(bz + idx);

            accum16(acc, cw, cax, cay, caz, cbx, cby, cbz);

            cw = nw; cax = nax; cay = nay; caz = naz;
            cbx = nbx; cby = nby; cbz = nbz;
        }
        // peeled final iteration — after this, acc is final and cw..cbz are dead
        accum16(acc, cw, cax, cay, caz, cbx, cby, cbz);

        const int b_cur = b;

        // prime the NEXT batch FIRST: its DRAM latency overlaps both the
        // butterfly reduce below and the QCP epilogue
        if (bpi + 1 < BPW) {
            b = wslot + (bpi + 1) * NWARPS_TOTAL;
            base3 = (size_t)b * 3 * NPTS;
            ax = (const float4*)(src  + base3);
            ay = (const float4*)(src  + base3 + NPTS);
            az = (const float4*)(src  + base3 + 2 * NPTS);
            bx = (const float4*)(corr + base3);
            by = (const float4*)(corr + base3 + NPTS);
            bz = (const float4*)(corr + base3 + 2 * NPTS);
            wp = (const float4*)(wts  + (size_t)b * NPTS);

            cw  = ldcs4(wp + lane);
            cax = ldcs4(ax + lane); cay = ldcs4(ay + lane); caz = ldcs4(az + lane);
            cbx = ldcs4(bx + lane); cby = ldcs4(by + lane); cbz = ldcs4(bz + lane);
        }

        // butterfly reduce: ALL lanes end with the complete 16 moments
#pragma unroll
        for (int i = 0; i < 16; i++) {
#pragma unroll
            for (int off = 16; off; off >>= 1)
                acc[i] += __shfl_xor_sync(0xffffffffu, acc[i], off);
        }

        // epilogue for the current batch (overlaps the primed loads above)
        qcp_write(acc, b_cur, lane, out);
    }
}

extern "C" void kernel_launch(void* const* d_in, const int* in_sizes, int n_in,
                              void* d_out, int out_size)
{
    const float* src  = (const float*)d_in[0];
    const float* corr = (const float*)d_in[1];
    const float* wts  = (const float*)d_in[2];
    float* out = (float*)d_out;

    kabsch_fused_kernel<<<GRID, THREADS>>>(src, corr, wts, out);
}